// round 12
// baseline (speedup 1.0000x reference)
#include <cuda_runtime.h>
#include <cuda_fp16.h>

#define H_IMG 1080
#define W_IMG 1920
#define GY 16
#define GX 16
#define GW 8
#define NPIX (H_IMG * W_IMG)

#define BX 384                      // threads per block
#define PXE 4                       // elements per thread
#define PXB 512                     // pixels per block
#define NC 6                        // x-cells per 512-px strip
#define NCELL (NC * GW)             // 48 cells, 144 slab entries

#define SX (15.0f / 1919.0f)
#define SY (15.0f / 1079.0f)

__device__ __forceinline__ float2 h2f(unsigned u) {
    __half2 h;
    *reinterpret_cast<unsigned*>(&h) = u;
    return __half22float2(h);
}
__device__ __forceinline__ unsigned f2h2(float a, float b) {
    __half2 h = __floats2half2_rn(a, b);
    return *reinterpret_cast<unsigned*>(&h);
}

__global__ __launch_bounds__(BX) void bilateral_grid_kernel(
    const float* __restrict__ rgb,
    const float* __restrict__ grids,
    const int*   __restrict__ idxp,
    float*       __restrict__ out)
{
    __shared__ __align__(16) uint4  slabh[NCELL * 3];   // 144 * 16B = 2304B
    __shared__ __align__(16) float4 xtab[PXB];          // 512 * 16B = 8KB

    const int tid   = threadIdx.x;
    const int row   = blockIdx.y;
    const int xpix0 = blockIdx.x * PXB;
    const int xbase = (int)((float)xpix0 * SX);

    const int q0 = tid / 3;
    const int c  = tid - 3 * q0;
    const int n0 = row * W_IMG + xpix0 + q0;

    // ---- rgb prefetch for up to 4 pixels ----
    float rr[PXE], gg[PXE], bb[PXE];
    bool  ok[PXE];
    #pragma unroll
    for (int k = 0; k < PXE; k++) {
        int px = xpix0 + q0 + k * 128;
        ok[k] = (px < W_IMG);
        if (ok[k]) {
            rr[k] = __ldcs(rgb + n0 + k * 128);
            gg[k] = __ldcs(rgb + NPIX + n0 + k * 128);
            bb[k] = __ldcs(rgb + 2 * NPIX + n0 + k * 128);
        } else { rr[k] = gg[k] = bb[k] = 0.f; }
    }

    // ---- slab build: 144 threads ----
    if (tid < NCELL * 3) {
        const float* grid = grids + (size_t)idxp[0] * (GY * GX * GW * 12);
        float gyv = (float)row * SY;
        float fy  = floorf(gyv);
        float wy  = gyv - fy;
        int y0 = min((int)fy, GY - 1);
        int y1 = min(y0 + 1, GY - 1);
        float wy0 = 1.0f - wy, wy1 = wy;

        int cell = tid / 3;
        int c4   = tid - cell * 3;
        int xq   = cell / GW;
        int zq   = cell - xq * GW;
        int zq1  = min(zq + 1, GW - 1);
        int xc   = min(xbase + xq, GX - 1);

        float4 a0 = __ldg(reinterpret_cast<const float4*>(
            grid + ((size_t)(y0 * GX + xc) * GW + zq)  * 12) + c4);
        float4 a1 = __ldg(reinterpret_cast<const float4*>(
            grid + ((size_t)(y1 * GX + xc) * GW + zq)  * 12) + c4);
        float4 b0 = __ldg(reinterpret_cast<const float4*>(
            grid + ((size_t)(y0 * GX + xc) * GW + zq1) * 12) + c4);
        float4 b1 = __ldg(reinterpret_cast<const float4*>(
            grid + ((size_t)(y1 * GX + xc) * GW + zq1) * 12) + c4);

        float4 v, nx;
        v.x  = wy0 * a0.x + wy1 * a1.x;  v.y  = wy0 * a0.y + wy1 * a1.y;
        v.z  = wy0 * a0.z + wy1 * a1.z;  v.w  = wy0 * a0.w + wy1 * a1.w;
        nx.x = wy0 * b0.x + wy1 * b1.x;  nx.y = wy0 * b0.y + wy1 * b1.y;
        nx.z = wy0 * b0.z + wy1 * b1.z;  nx.w = wy0 * b0.w + wy1 * b1.w;

        uint4 pk;
        pk.x = f2h2(v.x, v.y);
        pk.y = f2h2(v.z, v.w);
        pk.z = f2h2(nx.x - v.x, nx.y - v.y);
        pk.w = f2h2(nx.z - v.z, nx.w - v.w);
        slabh[tid] = pk;
    }

    // ---- x-table build: all threads, 2 passes ----
    #pragma unroll
    for (int t = tid; t < PXB; t += BX) {
        int x  = xpix0 + t;
        float gxv = (float)min(x, W_IMG - 1) * SX;
        float fx  = floorf(gxv);
        float wx  = gxv - fx;
        int xc0 = min((int)fx, GX - 1);
        int xc1 = min(xc0 + 1, GX - 1);
        int o0 = (xc0 - xbase) * (GW * 3);
        int o1 = (xc1 - xbase) * (GW * 3);
        xtab[t] = make_float4(wx, __int_as_float(o0), __int_as_float(o1), 0.0f);
    }
    __syncthreads();

    const size_t base3 = (size_t)(row * W_IMG + xpix0) * 3;
    float4* aff = reinterpret_cast<float4*>(out) + base3;
    float*  res = out + (size_t)12 * NPIX + base3;

    #pragma unroll
    for (int k = 0; k < PXE; k++) {
        if (!ok[k]) break;   // trailing elements only can be invalid
        float r = rr[k], g = gg[k], b = bb[k];

        float gray = 0.299f * r + 0.587f * g + 0.114f * b;
        float gz = __saturatef(gray) * 7.0f;
        float fz = floorf(gz);
        float wz = gz - fz;
        int z0 = (int)fz;

        float4 xe = xtab[q0 + k * 128];
        float wx  = xe.x;
        int zc = z0 * 3 + c;
        uint4 ua = slabh[__float_as_int(xe.y) + zc];
        uint4 ub = slabh[__float_as_int(xe.z) + zc];

        float w0 = 1.0f - wx;
        float2 va01 = h2f(ua.x), va23 = h2f(ua.y);
        float2 da01 = h2f(ua.z), da23 = h2f(ua.w);
        float2 vb01 = h2f(ub.x), vb23 = h2f(ub.y);
        float2 db01 = h2f(ub.z), db23 = h2f(ub.w);
        float4 a4;
        a4.x = fmaf(wx, fmaf(wz, db01.x, vb01.x), w0 * fmaf(wz, da01.x, va01.x));
        a4.y = fmaf(wx, fmaf(wz, db01.y, vb01.y), w0 * fmaf(wz, da01.y, va01.y));
        a4.z = fmaf(wx, fmaf(wz, db23.x, vb23.x), w0 * fmaf(wz, da23.x, va23.x));
        a4.w = fmaf(wx, fmaf(wz, db23.y, vb23.y), w0 * fmaf(wz, da23.y, va23.y));

        __stcs(aff + tid + k * BX, a4);
        __stcs(res + tid + k * BX,
               fmaf(a4.x, r, fmaf(a4.y, g, fmaf(a4.z, b, a4.w))));
    }
}

extern "C" void kernel_launch(void* const* d_in, const int* in_sizes, int n_in,
                              void* d_out, int out_size) {
    const float* rgb   = (const float*)d_in[0];
    const float* grids = (const float*)d_in[1];
    const int*   idx   = (const int*)d_in[2];
    float* out = (float*)d_out;

    dim3 grid((W_IMG + PXB - 1) / PXB, H_IMG);   // 4 x 1080
    bilateral_grid_kernel<<<grid, BX>>>(rgb, grids, idx, out);
}